// round 5
// baseline (speedup 1.0000x reference)
#include <cuda_runtime.h>
#include <cuda_bf16.h>
#include <cstdint>
#include <math.h>

#define N_ROWS 16384
#define C_ROWS 10000
#define D_DIM  256
#define KS     512          // stored cols: [hi(256) | lo(256)]
#define EPS    1e-6f

#define BM 128
#define BN 128
#define BK 64               // K elements per compute chunk (128B rows)
#define NCHUNK 12           // 3 terms x 4 chunks
#define STAGES 3
#define STAGE_BYTES 32768   // 16KB A + 16KB B
#define SMEM_TOTAL (STAGES * STAGE_BYTES)

// ---------------- device scratch (allocation-free rule) ----------------
__device__ float g_inv_xn[N_ROWS];
__device__ float g_inv_pn[C_ROWS];
__device__ __nv_bfloat16 g_Xs[(size_t)N_ROWS * KS];
__device__ __nv_bfloat16 g_Ps[(size_t)C_ROWS * KS];

// ---------------- helpers ----------------
__device__ __forceinline__ uint32_t smem_u32(const void* p) {
    uint32_t a;
    asm("{ .reg .u64 t; cvta.to.shared.u64 t, %1; cvt.u32.u64 %0, t; }" : "=r"(a) : "l"(p));
    return a;
}
__device__ __forceinline__ void cp_async16(uint32_t dst, const void* src, uint32_t src_bytes) {
    asm volatile("cp.async.cg.shared.global [%0], [%1], 16, %2;"
                 :: "r"(dst), "l"(src), "r"(src_bytes) : "memory");
}
#define CP_COMMIT() asm volatile("cp.async.commit_group;" ::: "memory")
template <int N>
__device__ __forceinline__ void cp_wait() {
    asm volatile("cp.async.wait_group %0;" :: "n"(N) : "memory");
}
__device__ __forceinline__ uint32_t sw128(uint32_t off) { return off ^ ((off >> 3) & 0x70); }

__device__ __forceinline__ void ldsm_x4(uint32_t* r, uint32_t addr) {
    asm volatile("ldmatrix.sync.aligned.m8n8.x4.shared.b16 {%0,%1,%2,%3}, [%4];"
                 : "=r"(r[0]), "=r"(r[1]), "=r"(r[2]), "=r"(r[3]) : "r"(addr));
}
__device__ __forceinline__ void ldsm_x2(uint32_t* r, uint32_t addr) {
    asm volatile("ldmatrix.sync.aligned.m8n8.x2.shared.b16 {%0,%1}, [%2];"
                 : "=r"(r[0]), "=r"(r[1]) : "r"(addr));
}
__device__ __forceinline__ void mma_bf16(float* d, const uint32_t* a, const uint32_t* b) {
    asm volatile("mma.sync.aligned.m16n8k16.row.col.f32.bf16.bf16.f32 "
                 "{%0,%1,%2,%3}, {%4,%5,%6,%7}, {%8,%9}, {%0,%1,%2,%3};"
                 : "+f"(d[0]), "+f"(d[1]), "+f"(d[2]), "+f"(d[3])
                 : "r"(a[0]), "r"(a[1]), "r"(a[2]), "r"(a[3]), "r"(b[0]), "r"(b[1]));
}

// ---------------- fused convert (hi/lo) + inverse-norm, warp per row ----------------
__global__ void convert_norm_kernel(const float* __restrict__ src,
                                    __nv_bfloat16* __restrict__ dst,
                                    float* __restrict__ inv_norm, int rows) {
    int warp = (blockIdx.x * blockDim.x + threadIdx.x) >> 5;
    int lane = threadIdx.x & 31;
    if (warp >= rows) return;
    const float4* p = reinterpret_cast<const float4*>(src + (size_t)warp * D_DIM);
    __nv_bfloat16* row = dst + (size_t)warp * KS;
    float sum = 0.f;
#pragma unroll
    for (int i = 0; i < 2; i++) {
        int j = lane + 32 * i;              // float4 index within row
        float4 v = p[j];
        float f[4] = {v.x, v.y, v.z, v.w};
        sum = fmaf(f[0], f[0], sum); sum = fmaf(f[1], f[1], sum);
        sum = fmaf(f[2], f[2], sum); sum = fmaf(f[3], f[3], sum);
        __nv_bfloat16 hi[4], lo[4];
#pragma unroll
        for (int q = 0; q < 4; q++) {
            hi[q] = __float2bfloat16_rn(f[q]);
            lo[q] = __float2bfloat16_rn(f[q] - __bfloat162float(hi[q]));
        }
        __nv_bfloat162 h01, h23, l01, l23;
        h01.x = hi[0]; h01.y = hi[1]; h23.x = hi[2]; h23.y = hi[3];
        l01.x = lo[0]; l01.y = lo[1]; l23.x = lo[2]; l23.y = lo[3];
        int c = j * 4;
        *reinterpret_cast<__nv_bfloat162*>(row + c) = h01;
        *reinterpret_cast<__nv_bfloat162*>(row + c + 2) = h23;
        *reinterpret_cast<__nv_bfloat162*>(row + 256 + c) = l01;
        *reinterpret_cast<__nv_bfloat162*>(row + 256 + c + 2) = l23;
    }
#pragma unroll
    for (int o = 16; o > 0; o >>= 1) sum += __shfl_xor_sync(0xffffffffu, sum, o);
    if (lane == 0) inv_norm[warp] = 1.0f / fmaxf(sqrtf(sum), EPS);
}

// ---------------- HMMA bf16 GEMM with fused cosine epilogue ----------------
// 128x128 tile, 8 warps in 2(M) x 4(N), warp tile 64x32.
// 12 virtual K-chunks: term 0 = Xhi*Phi, term 1 = Xhi*Plo, term 2 = Xlo*Phi.
__global__ __launch_bounds__(256, 2)
void cosine_hmma_kernel(const __nv_bfloat16* __restrict__ Xs,
                        const __nv_bfloat16* __restrict__ Ps,
                        const float* __restrict__ inv_xn,
                        const float* __restrict__ inv_pn,
                        float* __restrict__ out) {
    extern __shared__ __align__(1024) char smem[];
    const uint32_t sb = smem_u32(smem);
    const int tid = threadIdx.x;
    const int wid = tid >> 5;
    const int lane = tid & 31;
    const int m0 = blockIdx.y * BM;
    const int n0 = blockIdx.x * BN;

    const int wm = (wid & 1) * 64;
    const int wn = (wid >> 1) * 32;

    uint32_t aBase[4], bBase[4], aSel[4], bSel[4];
#pragma unroll
    for (int im = 0; im < 4; im++) {
        int rA = wm + im * 16 + (lane & 15);
        aBase[im] = rA * 128;
        aSel[im] = rA & 7;
    }
#pragma unroll
    for (int in = 0; in < 4; in++) {
        int rB = wn + in * 8 + (lane & 7);
        bBase[in] = 16384 + rB * 128;
        bSel[in] = rB & 7;
    }
    const uint32_t hiA = lane >> 4;
    const uint32_t hiB = (lane >> 3) & 1;

    float acc[4][4][4];
#pragma unroll
    for (int im = 0; im < 4; im++)
#pragma unroll
        for (int in = 0; in < 4; in++)
#pragma unroll
            for (int q = 0; q < 4; q++) acc[im][in][q] = 0.f;

    // chunk -> source K offsets in the [hi|lo] layout
    auto load_chunk = [&](int c, int s) {
        const int sub = (c & 3) * BK;
        const int aOff = sub + ((c >= 8) ? 256 : 0);              // A: hi,hi,lo
        const int bOff = sub + ((c >= 4 && c < 8) ? 256 : 0);     // B: hi,lo,hi
        const uint32_t aA = sb + s * STAGE_BYTES;
        const uint32_t bA = aA + 16384;
#pragma unroll
        for (int i = 0; i < 4; i++) {
            int u = tid + i * 256;
            int row = u >> 3, ch = u & 7;
            const char* g = (const char*)(Xs + (size_t)(m0 + row) * KS + aOff) + ch * 16;
            cp_async16(aA + sw128(row * 128 + ch * 16), g, 16);
        }
#pragma unroll
        for (int i = 0; i < 4; i++) {
            int u = tid + i * 256;
            int row = u >> 3, ch = u & 7;
            int pr = n0 + row;
            uint32_t ok = (pr < C_ROWS) ? 16u : 0u;
            const char* g = (const char*)(Ps + (size_t)(ok ? pr : 0) * KS + bOff) + ch * 16;
            cp_async16(bA + sw128(row * 128 + ch * 16), g, ok);
        }
        CP_COMMIT();
    };

    load_chunk(0, 0);
    load_chunk(1, 1);

    for (int c = 0; c < NCHUNK; c++) {
        const int s = c % STAGES;
        if (c == NCHUNK - 1) cp_wait<0>(); else cp_wait<1>();
        __syncthreads();   // stage c ready everywhere; all warps done with chunk c-1

        if (c + 2 < NCHUNK) load_chunk(c + 2, (c + 2) % STAGES);

        const uint32_t base = sb + s * STAGE_BYTES;
#pragma unroll
        for (int kk = 0; kk < 4; kk++) {
            uint32_t aF[4][4], bF[4][2];
#pragma unroll
            for (int im = 0; im < 4; im++)
                ldsm_x4(aF[im], base + aBase[im] + ((((kk * 2 + hiA) ^ aSel[im])) << 4));
#pragma unroll
            for (int in = 0; in < 4; in++)
                ldsm_x2(bF[in], base + bBase[in] + ((((kk * 2 + hiB) ^ bSel[in])) << 4));
#pragma unroll
            for (int im = 0; im < 4; im++)
#pragma unroll
                for (int in = 0; in < 4; in++)
                    mma_bf16(acc[im][in], aF[im], bF[in]);
        }
    }

    // ---- epilogue ----
    const int mrow0 = m0 + wm + (lane >> 2);
    const int ncol0 = n0 + wn + (lane & 3) * 2;
#pragma unroll
    for (int im = 0; im < 4; im++) {
        const int mA = mrow0 + im * 16;
        const float ixn0 = inv_xn[mA];
        const float ixn1 = inv_xn[mA + 8];
        float* orow0 = out + (size_t)mA * C_ROWS;
        float* orow1 = out + (size_t)(mA + 8) * C_ROWS;
#pragma unroll
        for (int in = 0; in < 4; in++) {
            const int n = ncol0 + in * 8;
            if (n < C_ROWS) {
                float2 ipn = *reinterpret_cast<const float2*>(inv_pn + n);
                float2 v0, v1;
                v0.x = acc[im][in][0] * ixn0 * ipn.x;
                v0.y = acc[im][in][1] * ixn0 * ipn.y;
                v1.x = acc[im][in][2] * ixn1 * ipn.x;
                v1.y = acc[im][in][3] * ixn1 * ipn.y;
                *reinterpret_cast<float2*>(orow0 + n) = v0;
                *reinterpret_cast<float2*>(orow1 + n) = v1;
            }
        }
    }
}

// ---------------- launch ----------------
extern "C" void kernel_launch(void* const* d_in, const int* in_sizes, int n_in,
                              void* d_out, int out_size) {
    const float* x = (const float*)d_in[0];         // [16384, 256]
    const float* protos = (const float*)d_in[1];    // [10000, 256]
    float* out = (float*)d_out;                     // [16384, 10000]

    float *inv_xn, *inv_pn;
    __nv_bfloat16 *Xs, *Ps;
    cudaGetSymbolAddress((void**)&inv_xn, g_inv_xn);
    cudaGetSymbolAddress((void**)&inv_pn, g_inv_pn);
    cudaGetSymbolAddress((void**)&Xs, g_Xs);
    cudaGetSymbolAddress((void**)&Ps, g_Ps);

    convert_norm_kernel<<<(N_ROWS * 32 + 255) / 256, 256>>>(x, Xs, inv_xn, N_ROWS);
    convert_norm_kernel<<<(C_ROWS * 32 + 255) / 256, 256>>>(protos, Ps, inv_pn, C_ROWS);

    cudaFuncSetAttribute(cosine_hmma_kernel,
                         cudaFuncAttributeMaxDynamicSharedMemorySize, SMEM_TOTAL);
    dim3 grid((C_ROWS + BN - 1) / BN, N_ROWS / BM);   // (79, 128)
    cosine_hmma_kernel<<<grid, 256, SMEM_TOTAL>>>(Xs, Ps, inv_xn, inv_pn, out);
}

// round 6
// speedup vs baseline: 1.4038x; 1.4038x over previous
#include <cuda_runtime.h>
#include <cuda_fp16.h>
#include <cstdint>
#include <math.h>

#define N_ROWS 16384
#define C_ROWS 10000
#define D_DIM  256
#define KSX    512          // X stored cols: [hi(256) | lo(256)]  (fp16)
#define KSP    256          // P stored cols: hi only              (fp16)
#define EPS    1e-6f

#define BM 128
#define BN 128
#define BK 64               // K elements per compute chunk (128B rows)
#define NCHUNK 8            // K=512 / 64
#define STAGES 3
#define STAGE_BYTES 32768   // 16KB A + 16KB B
#define SMEM_TOTAL (STAGES * STAGE_BYTES)

// ---------------- device scratch (allocation-free rule) ----------------
__device__ float g_inv_xn[N_ROWS];
__device__ float g_inv_pn[C_ROWS];
__device__ __half g_Xs[(size_t)N_ROWS * KSX];
__device__ __half g_Ps[(size_t)C_ROWS * KSP];

// ---------------- helpers ----------------
__device__ __forceinline__ uint32_t smem_u32(const void* p) {
    uint32_t a;
    asm("{ .reg .u64 t; cvta.to.shared.u64 t, %1; cvt.u32.u64 %0, t; }" : "=r"(a) : "l"(p));
    return a;
}
__device__ __forceinline__ void cp_async16(uint32_t dst, const void* src, uint32_t src_bytes) {
    asm volatile("cp.async.cg.shared.global [%0], [%1], 16, %2;"
                 :: "r"(dst), "l"(src), "r"(src_bytes) : "memory");
}
#define CP_COMMIT() asm volatile("cp.async.commit_group;" ::: "memory")
template <int N>
__device__ __forceinline__ void cp_wait() {
    asm volatile("cp.async.wait_group %0;" :: "n"(N) : "memory");
}
__device__ __forceinline__ uint32_t sw128(uint32_t off) { return off ^ ((off >> 3) & 0x70); }

__device__ __forceinline__ void ldsm_x4(uint32_t* r, uint32_t addr) {
    asm volatile("ldmatrix.sync.aligned.m8n8.x4.shared.b16 {%0,%1,%2,%3}, [%4];"
                 : "=r"(r[0]), "=r"(r[1]), "=r"(r[2]), "=r"(r[3]) : "r"(addr));
}
__device__ __forceinline__ void ldsm_x2(uint32_t* r, uint32_t addr) {
    asm volatile("ldmatrix.sync.aligned.m8n8.x2.shared.b16 {%0,%1}, [%2];"
                 : "=r"(r[0]), "=r"(r[1]) : "r"(addr));
}
__device__ __forceinline__ void mma_fp16(float* d, const uint32_t* a, const uint32_t* b) {
    asm volatile("mma.sync.aligned.m16n8k16.row.col.f32.f16.f16.f32 "
                 "{%0,%1,%2,%3}, {%4,%5,%6,%7}, {%8,%9}, {%0,%1,%2,%3};"
                 : "+f"(d[0]), "+f"(d[1]), "+f"(d[2]), "+f"(d[3])
                 : "r"(a[0]), "r"(a[1]), "r"(a[2]), "r"(a[3]), "r"(b[0]), "r"(b[1]));
}

// ---------------- X: fp16 hi/lo split + inverse-norm, warp per row ----------------
__global__ void convert_x_kernel(const float* __restrict__ src,
                                 __half* __restrict__ dst,
                                 float* __restrict__ inv_norm, int rows) {
    int warp = (blockIdx.x * blockDim.x + threadIdx.x) >> 5;
    int lane = threadIdx.x & 31;
    if (warp >= rows) return;
    const float4* p = reinterpret_cast<const float4*>(src + (size_t)warp * D_DIM);
    __half* row = dst + (size_t)warp * KSX;
    float sum = 0.f;
#pragma unroll
    for (int i = 0; i < 2; i++) {
        int j = lane + 32 * i;
        float4 v = p[j];
        float f[4] = {v.x, v.y, v.z, v.w};
        sum = fmaf(f[0], f[0], sum); sum = fmaf(f[1], f[1], sum);
        sum = fmaf(f[2], f[2], sum); sum = fmaf(f[3], f[3], sum);
        __half hi[4], lo[4];
#pragma unroll
        for (int q = 0; q < 4; q++) {
            hi[q] = __float2half_rn(f[q]);
            lo[q] = __float2half_rn(f[q] - __half2float(hi[q]));
        }
        __half2 h01, h23, l01, l23;
        h01.x = hi[0]; h01.y = hi[1]; h23.x = hi[2]; h23.y = hi[3];
        l01.x = lo[0]; l01.y = lo[1]; l23.x = lo[2]; l23.y = lo[3];
        int c = j * 4;
        *reinterpret_cast<__half2*>(row + c) = h01;
        *reinterpret_cast<__half2*>(row + c + 2) = h23;
        *reinterpret_cast<__half2*>(row + 256 + c) = l01;
        *reinterpret_cast<__half2*>(row + 256 + c + 2) = l23;
    }
#pragma unroll
    for (int o = 16; o > 0; o >>= 1) sum += __shfl_xor_sync(0xffffffffu, sum, o);
    if (lane == 0) inv_norm[warp] = 1.0f / fmaxf(sqrtf(sum), EPS);
}

// ---------------- P: fp16 hi + inverse-norm, warp per row ----------------
__global__ void convert_p_kernel(const float* __restrict__ src,
                                 __half* __restrict__ dst,
                                 float* __restrict__ inv_norm, int rows) {
    int warp = (blockIdx.x * blockDim.x + threadIdx.x) >> 5;
    int lane = threadIdx.x & 31;
    if (warp >= rows) return;
    const float4* p = reinterpret_cast<const float4*>(src + (size_t)warp * D_DIM);
    __half* row = dst + (size_t)warp * KSP;
    float sum = 0.f;
#pragma unroll
    for (int i = 0; i < 2; i++) {
        int j = lane + 32 * i;
        float4 v = p[j];
        float f[4] = {v.x, v.y, v.z, v.w};
        sum = fmaf(f[0], f[0], sum); sum = fmaf(f[1], f[1], sum);
        sum = fmaf(f[2], f[2], sum); sum = fmaf(f[3], f[3], sum);
        __half2 h01, h23;
        h01.x = __float2half_rn(f[0]); h01.y = __float2half_rn(f[1]);
        h23.x = __float2half_rn(f[2]); h23.y = __float2half_rn(f[3]);
        int c = j * 4;
        *reinterpret_cast<__half2*>(row + c) = h01;
        *reinterpret_cast<__half2*>(row + c + 2) = h23;
    }
#pragma unroll
    for (int o = 16; o > 0; o >>= 1) sum += __shfl_xor_sync(0xffffffffu, sum, o);
    if (lane == 0) inv_norm[warp] = 1.0f / fmaxf(sqrtf(sum), EPS);
}

// ---------------- HMMA fp16 GEMM with fused cosine epilogue ----------------
// 128x128 tile, 8 warps in 2(M) x 4(N), warp tile 64x32.
// 8 K-chunks: A walks [hi|lo] (512), B repeats hi (256) twice.
__global__ __launch_bounds__(256, 2)
void cosine_hmma_kernel(const __half* __restrict__ Xs,
                        const __half* __restrict__ Ps,
                        const float* __restrict__ inv_xn,
                        const float* __restrict__ inv_pn,
                        float* __restrict__ out) {
    extern __shared__ __align__(1024) char smem[];
    const uint32_t sb = smem_u32(smem);
    const int tid = threadIdx.x;
    const int wid = tid >> 5;
    const int lane = tid & 31;
    const int m0 = blockIdx.y * BM;
    const int n0 = blockIdx.x * BN;

    const int wm = (wid & 1) * 64;
    const int wn = (wid >> 1) * 32;

    uint32_t aBase[4], bBase[4], aSel[4], bSel[4];
#pragma unroll
    for (int im = 0; im < 4; im++) {
        int rA = wm + im * 16 + (lane & 15);
        aBase[im] = rA * 128;
        aSel[im] = rA & 7;
    }
#pragma unroll
    for (int in = 0; in < 4; in++) {
        int rB = wn + in * 8 + (lane & 7);
        bBase[in] = 16384 + rB * 128;
        bSel[in] = rB & 7;
    }
    const uint32_t hiA = lane >> 4;
    const uint32_t hiB = (lane >> 3) & 1;

    float acc[4][4][4];
#pragma unroll
    for (int im = 0; im < 4; im++)
#pragma unroll
        for (int in = 0; in < 4; in++)
#pragma unroll
            for (int q = 0; q < 4; q++) acc[im][in][q] = 0.f;

    auto load_chunk = [&](int c, int s) {
        const int aOff = c * BK;            // 0..448 within [hi|lo]
        const int bOff = (c & 3) * BK;      // 0..192 within hi
        const uint32_t aA = sb + s * STAGE_BYTES;
        const uint32_t bA = aA + 16384;
#pragma unroll
        for (int i = 0; i < 4; i++) {
            int u = tid + i * 256;
            int row = u >> 3, ch = u & 7;
            const char* g = (const char*)(Xs + (size_t)(m0 + row) * KSX + aOff) + ch * 16;
            cp_async16(aA + sw128(row * 128 + ch * 16), g, 16);
        }
#pragma unroll
        for (int i = 0; i < 4; i++) {
            int u = tid + i * 256;
            int row = u >> 3, ch = u & 7;
            int pr = n0 + row;
            uint32_t ok = (pr < C_ROWS) ? 16u : 0u;
            const char* g = (const char*)(Ps + (size_t)(ok ? pr : 0) * KSP + bOff) + ch * 16;
            cp_async16(bA + sw128(row * 128 + ch * 16), g, ok);
        }
        CP_COMMIT();
    };

    load_chunk(0, 0);
    load_chunk(1, 1);

    for (int c = 0; c < NCHUNK; c++) {
        const int s = c % STAGES;
        if (c == NCHUNK - 1) cp_wait<0>(); else cp_wait<1>();
        __syncthreads();   // stage c ready; all warps done with chunk c-1

        if (c + 2 < NCHUNK) load_chunk(c + 2, (c + 2) % STAGES);

        const uint32_t base = sb + s * STAGE_BYTES;
#pragma unroll
        for (int kk = 0; kk < 4; kk++) {
            uint32_t aF[4][4], bF[4][2];
#pragma unroll
            for (int im = 0; im < 4; im++)
                ldsm_x4(aF[im], base + aBase[im] + ((((kk * 2 + hiA) ^ aSel[im])) << 4));
#pragma unroll
            for (int in = 0; in < 4; in++)
                ldsm_x2(bF[in], base + bBase[in] + ((((kk * 2 + hiB) ^ bSel[in])) << 4));
#pragma unroll
            for (int im = 0; im < 4; im++)
#pragma unroll
                for (int in = 0; in < 4; in++)
                    mma_fp16(acc[im][in], aF[im], bF[in]);
        }
    }

    // ---- epilogue ----
    const int mrow0 = m0 + wm + (lane >> 2);
    const int ncol0 = n0 + wn + (lane & 3) * 2;
#pragma unroll
    for (int im = 0; im < 4; im++) {
        const int mA = mrow0 + im * 16;
        const float ixn0 = inv_xn[mA];
        const float ixn1 = inv_xn[mA + 8];
        float* orow0 = out + (size_t)mA * C_ROWS;
        float* orow1 = out + (size_t)(mA + 8) * C_ROWS;
#pragma unroll
        for (int in = 0; in < 4; in++) {
            const int n = ncol0 + in * 8;
            if (n < C_ROWS) {
                float2 ipn = *reinterpret_cast<const float2*>(inv_pn + n);
                float2 v0, v1;
                v0.x = acc[im][in][0] * ixn0 * ipn.x;
                v0.y = acc[im][in][1] * ixn0 * ipn.y;
                v1.x = acc[im][in][2] * ixn1 * ipn.x;
                v1.y = acc[im][in][3] * ixn1 * ipn.y;
                *reinterpret_cast<float2*>(orow0 + n) = v0;
                *reinterpret_cast<float2*>(orow1 + n) = v1;
            }
        }
    }
}

// ---------------- launch ----------------
extern "C" void kernel_launch(void* const* d_in, const int* in_sizes, int n_in,
                              void* d_out, int out_size) {
    const float* x = (const float*)d_in[0];         // [16384, 256]
    const float* protos = (const float*)d_in[1];    // [10000, 256]
    float* out = (float*)d_out;                     // [16384, 10000]

    float *inv_xn, *inv_pn;
    __half *Xs, *Ps;
    cudaGetSymbolAddress((void**)&inv_xn, g_inv_xn);
    cudaGetSymbolAddress((void**)&inv_pn, g_inv_pn);
    cudaGetSymbolAddress((void**)&Xs, g_Xs);
    cudaGetSymbolAddress((void**)&Ps, g_Ps);

    convert_x_kernel<<<(N_ROWS * 32 + 255) / 256, 256>>>(x, Xs, inv_xn, N_ROWS);
    convert_p_kernel<<<(C_ROWS * 32 + 255) / 256, 256>>>(protos, Ps, inv_pn, C_ROWS);

    cudaFuncSetAttribute(cosine_hmma_kernel,
                         cudaFuncAttributeMaxDynamicSharedMemorySize, SMEM_TOTAL);
    dim3 grid((C_ROWS + BN - 1) / BN, N_ROWS / BM);   // (79, 128)
    cosine_hmma_kernel<<<grid, 256, SMEM_TOTAL>>>(Xs, Ps, inv_xn, inv_pn, out);
}

// round 7
// speedup vs baseline: 2.3796x; 1.6951x over previous
#include <cuda_runtime.h>
#include <cuda_fp16.h>
#include <cstdint>
#include <math.h>

#define N_ROWS 16384
#define C_ROWS 10000
#define D_DIM  256
#define EPS    1e-6f

#define BM 128
#define BN 128
#define BK 64               // K elements per compute chunk (128B rows)
#define NCHUNK 4            // K=256 / 64
#define STAGES 3
#define STAGE_BYTES 32768   // 16KB A + 16KB B
#define SMEM_TOTAL (STAGES * STAGE_BYTES)

// ---------------- device scratch (allocation-free rule) ----------------
__device__ float g_inv_xn[N_ROWS];
__device__ float g_inv_pn[C_ROWS];
__device__ __half g_Xs[(size_t)N_ROWS * D_DIM];
__device__ __half g_Ps[(size_t)C_ROWS * D_DIM];

// ---------------- helpers ----------------
__device__ __forceinline__ uint32_t smem_u32(const void* p) {
    uint32_t a;
    asm("{ .reg .u64 t; cvta.to.shared.u64 t, %1; cvt.u32.u64 %0, t; }" : "=r"(a) : "l"(p));
    return a;
}
__device__ __forceinline__ void cp_async16(uint32_t dst, const void* src, uint32_t src_bytes) {
    asm volatile("cp.async.cg.shared.global [%0], [%1], 16, %2;"
                 :: "r"(dst), "l"(src), "r"(src_bytes) : "memory");
}
#define CP_COMMIT() asm volatile("cp.async.commit_group;" ::: "memory")
template <int N>
__device__ __forceinline__ void cp_wait() {
    asm volatile("cp.async.wait_group %0;" :: "n"(N) : "memory");
}
__device__ __forceinline__ uint32_t sw128(uint32_t off) { return off ^ ((off >> 3) & 0x70); }

__device__ __forceinline__ void ldsm_x4(uint32_t* r, uint32_t addr) {
    asm volatile("ldmatrix.sync.aligned.m8n8.x4.shared.b16 {%0,%1,%2,%3}, [%4];"
                 : "=r"(r[0]), "=r"(r[1]), "=r"(r[2]), "=r"(r[3]) : "r"(addr));
}
__device__ __forceinline__ void ldsm_x2(uint32_t* r, uint32_t addr) {
    asm volatile("ldmatrix.sync.aligned.m8n8.x2.shared.b16 {%0,%1}, [%2];"
                 : "=r"(r[0]), "=r"(r[1]) : "r"(addr));
}
__device__ __forceinline__ void mma_fp16(float* d, const uint32_t* a, const uint32_t* b) {
    asm volatile("mma.sync.aligned.m16n8k16.row.col.f32.f16.f16.f32 "
                 "{%0,%1,%2,%3}, {%4,%5,%6,%7}, {%8,%9}, {%0,%1,%2,%3};"
                 : "+f"(d[0]), "+f"(d[1]), "+f"(d[2]), "+f"(d[3])
                 : "r"(a[0]), "r"(a[1]), "r"(a[2]), "r"(a[3]), "r"(b[0]), "r"(b[1]));
}

// ---------------- fp16 convert + inverse-norm, warp per row ----------------
__global__ void convert_norm_kernel(const float* __restrict__ src,
                                    __half* __restrict__ dst,
                                    float* __restrict__ inv_norm, int rows) {
    int warp = (blockIdx.x * blockDim.x + threadIdx.x) >> 5;
    int lane = threadIdx.x & 31;
    if (warp >= rows) return;
    const float4* p = reinterpret_cast<const float4*>(src + (size_t)warp * D_DIM);
    __half* row = dst + (size_t)warp * D_DIM;
    float sum = 0.f;
#pragma unroll
    for (int i = 0; i < 2; i++) {
        int j = lane + 32 * i;
        float4 v = p[j];
        float f[4] = {v.x, v.y, v.z, v.w};
        sum = fmaf(f[0], f[0], sum); sum = fmaf(f[1], f[1], sum);
        sum = fmaf(f[2], f[2], sum); sum = fmaf(f[3], f[3], sum);
        __half2 h01, h23;
        h01.x = __float2half_rn(f[0]); h01.y = __float2half_rn(f[1]);
        h23.x = __float2half_rn(f[2]); h23.y = __float2half_rn(f[3]);
        int c = j * 4;
        *reinterpret_cast<__half2*>(row + c) = h01;
        *reinterpret_cast<__half2*>(row + c + 2) = h23;
    }
#pragma unroll
    for (int o = 16; o > 0; o >>= 1) sum += __shfl_xor_sync(0xffffffffu, sum, o);
    if (lane == 0) inv_norm[warp] = 1.0f / fmaxf(sqrtf(sum), EPS);
}

// ---------------- HMMA fp16 GEMM with fused cosine epilogue ----------------
// 128x128 tile, 8 warps in 2(M) x 4(N), warp tile 64x32, K=256 in 4 chunks.
__global__ __launch_bounds__(256, 2)
void cosine_hmma_kernel(const __half* __restrict__ Xs,
                        const __half* __restrict__ Ps,
                        const float* __restrict__ inv_xn,
                        const float* __restrict__ inv_pn,
                        float* __restrict__ out) {
    extern __shared__ __align__(1024) char smem[];
    const uint32_t sb = smem_u32(smem);
    const int tid = threadIdx.x;
    const int wid = tid >> 5;
    const int lane = tid & 31;
    const int m0 = blockIdx.y * BM;
    const int n0 = blockIdx.x * BN;

    const int wm = (wid & 1) * 64;
    const int wn = (wid >> 1) * 32;

    uint32_t aBase[4], bBase[4], aSel[4], bSel[4];
#pragma unroll
    for (int im = 0; im < 4; im++) {
        int rA = wm + im * 16 + (lane & 15);
        aBase[im] = rA * 128;
        aSel[im] = rA & 7;
    }
#pragma unroll
    for (int in = 0; in < 4; in++) {
        int rB = wn + in * 8 + (lane & 7);
        bBase[in] = 16384 + rB * 128;
        bSel[in] = rB & 7;
    }
    const uint32_t hiA = lane >> 4;
    const uint32_t hiB = (lane >> 3) & 1;

    float acc[4][4][4];
#pragma unroll
    for (int im = 0; im < 4; im++)
#pragma unroll
        for (int in = 0; in < 4; in++)
#pragma unroll
            for (int q = 0; q < 4; q++) acc[im][in][q] = 0.f;

    auto load_chunk = [&](int c, int s) {
        const int kOff = c * BK;
        const uint32_t aA = sb + s * STAGE_BYTES;
        const uint32_t bA = aA + 16384;
#pragma unroll
        for (int i = 0; i < 4; i++) {
            int u = tid + i * 256;
            int row = u >> 3, ch = u & 7;
            const char* g = (const char*)(Xs + (size_t)(m0 + row) * D_DIM + kOff) + ch * 16;
            cp_async16(aA + sw128(row * 128 + ch * 16), g, 16);
        }
#pragma unroll
        for (int i = 0; i < 4; i++) {
            int u = tid + i * 256;
            int row = u >> 3, ch = u & 7;
            int pr = n0 + row;
            uint32_t ok = (pr < C_ROWS) ? 16u : 0u;
            const char* g = (const char*)(Ps + (size_t)(ok ? pr : 0) * D_DIM + kOff) + ch * 16;
            cp_async16(bA + sw128(row * 128 + ch * 16), g, ok);
        }
        CP_COMMIT();
    };

    load_chunk(0, 0);
    load_chunk(1, 1);

    for (int c = 0; c < NCHUNK; c++) {
        const int s = c % STAGES;
        if (c == NCHUNK - 1) cp_wait<0>(); else cp_wait<1>();
        __syncthreads();   // stage c ready; all warps done with chunk c-1

        if (c + 2 < NCHUNK) load_chunk(c + 2, (c + 2) % STAGES);

        const uint32_t base = sb + s * STAGE_BYTES;
#pragma unroll
        for (int kk = 0; kk < 4; kk++) {
            uint32_t aF[4][4], bF[4][2];
#pragma unroll
            for (int im = 0; im < 4; im++)
                ldsm_x4(aF[im], base + aBase[im] + ((((kk * 2 + hiA) ^ aSel[im])) << 4));
#pragma unroll
            for (int in = 0; in < 4; in++)
                ldsm_x2(bF[in], base + bBase[in] + ((((kk * 2 + hiB) ^ bSel[in])) << 4));
#pragma unroll
            for (int im = 0; im < 4; im++)
#pragma unroll
                for (int in = 0; in < 4; in++)
                    mma_fp16(acc[im][in], aF[im], bF[in]);
        }
    }

    // ---- epilogue ----
    const int mrow0 = m0 + wm + (lane >> 2);
    const int ncol0 = n0 + wn + (lane & 3) * 2;
#pragma unroll
    for (int im = 0; im < 4; im++) {
        const int mA = mrow0 + im * 16;
        const float ixn0 = inv_xn[mA];
        const float ixn1 = inv_xn[mA + 8];
        float* orow0 = out + (size_t)mA * C_ROWS;
        float* orow1 = out + (size_t)(mA + 8) * C_ROWS;
#pragma unroll
        for (int in = 0; in < 4; in++) {
            const int n = ncol0 + in * 8;
            if (n < C_ROWS) {
                float2 ipn = *reinterpret_cast<const float2*>(inv_pn + n);
                float2 v0, v1;
                v0.x = acc[im][in][0] * ixn0 * ipn.x;
                v0.y = acc[im][in][1] * ixn0 * ipn.y;
                v1.x = acc[im][in][2] * ixn1 * ipn.x;
                v1.y = acc[im][in][3] * ixn1 * ipn.y;
                *reinterpret_cast<float2*>(orow0 + n) = v0;
                *reinterpret_cast<float2*>(orow1 + n) = v1;
            }
        }
    }
}

// ---------------- launch ----------------
extern "C" void kernel_launch(void* const* d_in, const int* in_sizes, int n_in,
                              void* d_out, int out_size) {
    const float* x = (const float*)d_in[0];         // [16384, 256]
    const float* protos = (const float*)d_in[1];    // [10000, 256]
    float* out = (float*)d_out;                     // [16384, 10000]

    float *inv_xn, *inv_pn;
    __half *Xs, *Ps;
    cudaGetSymbolAddress((void**)&inv_xn, g_inv_xn);
    cudaGetSymbolAddress((void**)&inv_pn, g_inv_pn);
    cudaGetSymbolAddress((void**)&Xs, g_Xs);
    cudaGetSymbolAddress((void**)&Ps, g_Ps);

    convert_norm_kernel<<<(N_ROWS * 32 + 255) / 256, 256>>>(x, Xs, inv_xn, N_ROWS);
    convert_norm_kernel<<<(C_ROWS * 32 + 255) / 256, 256>>>(protos, Ps, inv_pn, C_ROWS);

    cudaFuncSetAttribute(cosine_hmma_kernel,
                         cudaFuncAttributeMaxDynamicSharedMemorySize, SMEM_TOTAL);
    dim3 grid((C_ROWS + BN - 1) / BN, N_ROWS / BM);   // (79, 128)
    cosine_hmma_kernel<<<grid, 256, SMEM_TOTAL>>>(Xs, Ps, inv_xn, inv_pn, out);
}